// round 2
// baseline (speedup 1.0000x reference)
#include <cuda_runtime.h>
#include <cstdint>

#define NB        512
#define NC        480
#define NP        15
#define NHW       225                    // 15*15
#define HALF_C    240
#define HALF_EL   (HALF_C * NHW)         // 54000 floats per CTA
#define SLICE     (NC * NHW)             // 108000 floats per batch
#define NTHREADS  1024

// smem layout (floats): s_x[54000] | s_mean[480] | s_cent[480] | s_at[244 pad]
#define OFF_MEAN  HALF_EL
#define OFF_CENT  (HALF_EL + NC)
#define OFF_AT    (HALF_EL + 2 * NC)
#define SMEM_FLOATS (HALF_EL + 2 * NC + 244)
#define DYN_SMEM  (SMEM_FLOATS * 4)      // 220816 B

__device__ __forceinline__ uint32_t smem_u32(const void* p) {
    uint32_t a;
    asm("{ .reg .u64 t; cvta.to.shared.u64 t, %1; cvt.u32.u64 %0, t; }"
        : "=r"(a) : "l"(p));
    return a;
}

__device__ __forceinline__ void dsmem_store_f32(uint32_t local_addr, uint32_t peer_rank, float v) {
    uint32_t remote;
    asm volatile("mapa.shared::cluster.u32 %0, %1, %2;"
                 : "=r"(remote) : "r"(local_addr), "r"(peer_rank));
    asm volatile("st.shared::cluster.f32 [%0], %1;"
                 :: "r"(remote), "f"(v) : "memory");
}

__global__ __launch_bounds__(NTHREADS, 1) __cluster_dims__(2, 1, 1)
void ncam3d_cluster_kernel(const float* __restrict__ x,
                           const float* __restrict__ w1, const float* __restrict__ b1,
                           const float* __restrict__ w2, const float* __restrict__ b2,
                           float* __restrict__ out)
{
    extern __shared__ float smem[];
    float* s_x    = smem;
    float* s_mean = smem + OFF_MEAN;   // [480] global-channel indexed
    float* s_cent = smem + OFF_CENT;   // [480]
    float* s_at   = smem + OFF_AT;     // [241] local-channel indexed (+pad)

    uint32_t rank;
    asm("mov.u32 %0, %%cluster_ctarank;" : "=r"(rank));
    const int b   = blockIdx.x >> 1;
    const int tid = threadIdx.x;
    const int warp = tid >> 5;
    const int lane = tid & 31;

    const float* __restrict__ xb = x   + (size_t)b * SLICE + (size_t)rank * HALF_EL;
    float* __restrict__       ob = out + (size_t)b * SLICE + (size_t)rank * HALF_EL;

    // ---------- Phase 1: stream gmem -> smem (pure copy, max MLP) ----------
    {
        const float4* __restrict__ xv = (const float4*)xb;
        float4* sv = (float4*)s_x;
        #pragma unroll 4
        for (int i = tid; i < HALF_EL / 4; i += NTHREADS)
            sv[i] = xv[i];
    }
    __syncthreads();

    // ---------- Phase 2: per-channel reductions from smem ------------------
    for (int cl = warp; cl < HALF_C; cl += (NTHREADS / 32)) {
        const float* row = s_x + cl * NHW;
        float sf = 0.f, sc = 0.f;
        for (int i = lane; i < NHW; i += 32) {
            float v = row[i];
            sf += v;
            int h = i / NP;
            int w = i - h * NP;
            if ((unsigned)(h - 6) < 3u && (unsigned)(w - 6) < 3u) sc += v;
        }
        #pragma unroll
        for (int off = 16; off; off >>= 1) {
            sf += __shfl_xor_sync(0xffffffffu, sf, off);
            sc += __shfl_xor_sync(0xffffffffu, sc, off);
        }
        if (lane == 0) {
            const int gc = rank * HALF_C + cl;
            float mf = sf * (1.0f / 225.0f);
            float mc = sc * (1.0f / 225.0f);
            s_mean[gc] = mf;
            s_cent[gc] = mc;
            // push to peer CTA's smem at the same offsets
            uint32_t a_mean = smem_u32(&s_mean[gc]);
            uint32_t a_cent = smem_u32(&s_cent[gc]);
            dsmem_store_f32(a_mean, rank ^ 1u, mf);
            dsmem_store_f32(a_cent, rank ^ 1u, mc);
        }
    }

    // cluster barrier: all DSMEM pushes visible to both CTAs
    asm volatile("barrier.cluster.arrive.aligned;" ::: "memory");
    asm volatile("barrier.cluster.wait.aligned;" ::: "memory");

    // ---------- Phase 3: gates for this CTA's 240 channels -----------------
    if (tid < HALF_C) {
        const int gc = rank * HALF_C + tid;
        float acc1 = __ldg(b1);
        float acc2 = __ldg(b2);
        #pragma unroll
        for (int k = 0; k < 5; k++) {
            int j = gc + k - 2;
            if ((unsigned)j < (unsigned)NC) {
                acc1 = fmaf(__ldg(w1 + k),     s_mean[j],          acc1);
                acc1 = fmaf(__ldg(w1 + 5 + k), s_mean[NC - 1 - j], acc1);
                acc2 = fmaf(__ldg(w2 + k),     s_cent[j],          acc2);
                acc2 = fmaf(__ldg(w2 + 5 + k), s_cent[NC - 1 - j], acc2);
            }
        }
        float a1 = 1.0f / (1.0f + __expf(-acc1));
        float a2 = 1.0f / (1.0f + __expf(-acc2));
        float p  = (a1 * a2 - 0.2f) * 2.0f;
        s_at[tid] = 1.0f / (1.0f + __expf(-p));
    } else if (tid == HALF_C) {
        s_at[HALF_C] = 0.f;   // pad (read speculatively, never used)
    }
    __syncthreads();

    // ---------- Phase 4: scale from smem, stream to gmem -------------------
    {
        const float4* sv = (const float4*)s_x;
        float4* __restrict__ ov = (float4*)ob;
        #pragma unroll 4
        for (int i = tid; i < HALF_EL / 4; i += NTHREADS) {
            float4 v = sv[i];
            int e  = i * 4;
            int c0 = e / NHW;           // local channel
            int r  = e - c0 * NHW;
            float a0 = s_at[c0];
            float an = s_at[c0 + 1];
            v.x *= a0;
            v.y *= (r + 1 < NHW) ? a0 : an;
            v.z *= (r + 2 < NHW) ? a0 : an;
            v.w *= (r + 3 < NHW) ? a0 : an;
            ov[i] = v;
        }
    }
}

extern "C" void kernel_launch(void* const* d_in, const int* in_sizes, int n_in,
                              void* d_out, int out_size)
{
    const float* x  = (const float*)d_in[0];
    const float* w1 = (const float*)d_in[1];
    const float* b1 = (const float*)d_in[2];
    const float* w2 = (const float*)d_in[3];
    const float* b2 = (const float*)d_in[4];
    float* out = (float*)d_out;

    static int configured = 0;
    cudaFuncSetAttribute(ncam3d_cluster_kernel,
                         cudaFuncAttributeMaxDynamicSharedMemorySize, DYN_SMEM);
    (void)configured;

    ncam3d_cluster_kernel<<<NB * 2, NTHREADS, DYN_SMEM>>>(x, w1, b1, w2, b2, out);
}

// round 3
// speedup vs baseline: 1.3446x; 1.3446x over previous
#include <cuda_runtime.h>

#define NB   512
#define NC   480
#define NP   15
#define NHW  225                  // 15*15
#define SLICE (NC * NHW)          // 108000 floats per batch
#define NTHREADS 1024

__global__ __launch_bounds__(NTHREADS, 2)   // cap regs at 32 -> 2 CTAs/SM
void ncam3d_kernel(const float* __restrict__ x,
                   const float* __restrict__ w1, const float* __restrict__ b1,
                   const float* __restrict__ w2, const float* __restrict__ b2,
                   float* __restrict__ out)
{
    __shared__ float s_full[NC];      // full-slice means
    __shared__ float s_cent[NC];      // center-3x3 means
    __shared__ float s_at[NC + 1];    // gate per channel (+pad for vec crossing)

    const int b   = blockIdx.x;
    const float* __restrict__ xb = x + (size_t)b * SLICE;
    float* __restrict__       ob = out + (size_t)b * SLICE;
    const int tid  = threadIdx.x;
    const int warp = tid >> 5;
    const int lane = tid & 31;

    // ---------------- Phase 1: per-channel reductions (warp per channel) ----
    for (int c = warp; c < NC; c += (NTHREADS / 32)) {
        const float* row = xb + c * NHW;
        float sf = 0.f, sc = 0.f;
        for (int i = lane; i < NHW; i += 32) {
            float v = __ldg(row + i);
            sf += v;
            int h = i / NP;
            int w = i - h * NP;
            // ring mask d=6, n=15 => center 3x3 (h,w in [6,8])
            if ((unsigned)(h - 6) < 3u && (unsigned)(w - 6) < 3u) sc += v;
        }
        #pragma unroll
        for (int off = 16; off; off >>= 1) {
            sf += __shfl_xor_sync(0xffffffffu, sf, off);
            sc += __shfl_xor_sync(0xffffffffu, sc, off);
        }
        if (lane == 0) {
            s_full[c] = sf * (1.0f / 225.0f);
            s_cent[c] = sc * (1.0f / 225.0f);
        }
    }
    __syncthreads();

    // ---------------- Phase 2: gate per channel (conv 2x5 over channels) ----
    if (tid < NC) {
        const int c = tid;
        float acc1 = __ldg(b1);
        float acc2 = __ldg(b2);
        #pragma unroll
        for (int k = 0; k < 5; k++) {
            int j = c + k - 2;
            if ((unsigned)j < (unsigned)NC) {
                acc1 = fmaf(__ldg(w1 + k),     s_full[j],          acc1);
                acc1 = fmaf(__ldg(w1 + 5 + k), s_full[NC - 1 - j], acc1);
                acc2 = fmaf(__ldg(w2 + k),     s_cent[j],          acc2);
                acc2 = fmaf(__ldg(w2 + 5 + k), s_cent[NC - 1 - j], acc2);
            }
        }
        float a1 = 1.0f / (1.0f + __expf(-acc1));
        float a2 = 1.0f / (1.0f + __expf(-acc2));
        float p  = (a1 * a2 - 0.2f) * 2.0f;
        s_at[c]  = 1.0f / (1.0f + __expf(-p));
    } else if (tid == NC) {
        s_at[NC] = 0.f;   // pad: read speculatively at slice end, never used
    }
    __syncthreads();

    // ---------------- Phase 3: scale + write (vectorized streaming) ---------
    const float4* __restrict__ xv = (const float4*)xb;
    float4* __restrict__       ov = (float4*)ob;
    #pragma unroll 2
    for (int i = tid; i < SLICE / 4; i += NTHREADS) {
        float4 v = xv[i];
        int e  = i * 4;
        int c0 = e / NHW;            // constant division -> mul/shift
        int r  = e - c0 * NHW;
        float a0 = s_at[c0];
        float an = s_at[c0 + 1];     // padded; only used when crossing
        v.x *= a0;
        v.y *= (r + 1 < NHW) ? a0 : an;
        v.z *= (r + 2 < NHW) ? a0 : an;
        v.w *= (r + 3 < NHW) ? a0 : an;
        ov[i] = v;
    }
}

extern "C" void kernel_launch(void* const* d_in, const int* in_sizes, int n_in,
                              void* d_out, int out_size)
{
    const float* x  = (const float*)d_in[0];
    const float* w1 = (const float*)d_in[1];
    const float* b1 = (const float*)d_in[2];
    const float* w2 = (const float*)d_in[3];
    const float* b2 = (const float*)d_in[4];
    float* out = (float*)d_out;

    ncam3d_kernel<<<NB, NTHREADS>>>(x, w1, b1, w2, b2, out);
}